// round 16
// baseline (speedup 1.0000x reference)
#include <cuda_runtime.h>
#include <cuda_fp16.h>
#include <math.h>
#include <stdint.h>

#define TT     4096      // total tokens B*S
#define HIDDIM 3584
#define NH     16
#define NKV    8
#define HD     256
#define SEQ    2048
#define NB     2
#define QKVW   8192      // (NH + 2*NKV) * HD
#define ATTW   4096      // NH * HD
#define WIN    1024
#define SCALE  0.0625f   // 256^-0.5
#define SOFTCAP 50.0f

#define BQ 64
#define BK 64

#define WSCALE 32.0f
#define CSCALE (1.0f / 32.0f)

// ---------------- scratch (static device allocations) ----------------------
__device__ float g_qkv[(size_t)TT * QKVW];

// fp16 attention operand planes, layout [head][t][d]
__device__ __half g_qh[(size_t)NH * TT * HD];
__device__ __half g_ql[(size_t)NH * TT * HD];
__device__ __half g_kh[(size_t)NKV * TT * HD];
__device__ __half g_kl[(size_t)NKV * TT * HD];
__device__ __half g_vh[(size_t)NKV * TT * HD];

// fp16 split planes for projections
__device__ __half g_hidH[(size_t)TT * HIDDIM];
__device__ __half g_hidL[(size_t)TT * HIDDIM];
__device__ __half g_wqH[(size_t)QKVW * HIDDIM];
__device__ __half g_wqL[(size_t)QKVW * HIDDIM];
__device__ __half g_aH[(size_t)TT * ATTW];
__device__ __half g_aL[(size_t)TT * ATTW];
__device__ __half g_woH[(size_t)HIDDIM * ATTW];
__device__ __half g_woL[(size_t)HIDDIM * ATTW];

// ---------------------------------------------------------------------------
// fp32 -> fp16 hi/lo split (with pre-scale)
// ---------------------------------------------------------------------------
__global__ __launch_bounds__(256) void split_f16(
    const float* __restrict__ src,
    __half* __restrict__ hi, __half* __restrict__ lo, float scale, size_t n)
{
    size_t i = ((size_t)blockIdx.x * blockDim.x + threadIdx.x) * 4;
    if (i >= n) return;
    float4 v = *(const float4*)(src + i);
    v.x *= scale; v.y *= scale; v.z *= scale; v.w *= scale;
    __half h0 = __float2half(v.x), h1 = __float2half(v.y);
    __half h2 = __float2half(v.z), h3 = __float2half(v.w);
    __half l0 = __float2half(v.x - __half2float(h0));
    __half l1 = __float2half(v.y - __half2float(h1));
    __half l2 = __float2half(v.z - __half2float(h2));
    __half l3 = __float2half(v.w - __half2float(h3));
    *(__half2*)(hi + i)     = __halves2half2(h0, h1);
    *(__half2*)(hi + i + 2) = __halves2half2(h2, h3);
    *(__half2*)(lo + i)     = __halves2half2(l0, l1);
    *(__half2*)(lo + i + 2) = __halves2half2(l2, l3);
}

// ---------------------------------------------------------------------------
// helpers
// ---------------------------------------------------------------------------
__device__ __forceinline__ uint32_t smem_u32(const void* p) {
    uint32_t a;
    asm("{ .reg .u64 t; cvta.to.shared.u64 t, %1; cvt.u32.u64 %0, t; }"
        : "=r"(a) : "l"(p));
    return a;
}
__device__ __forceinline__ void ldsm_x4(uint32_t* r, uint32_t addr) {
    asm volatile("ldmatrix.sync.aligned.m8n8.x4.shared.b16 {%0,%1,%2,%3}, [%4];"
                 : "=r"(r[0]), "=r"(r[1]), "=r"(r[2]), "=r"(r[3]) : "r"(addr));
}
__device__ __forceinline__ void ldsm_x4t(uint32_t* r, uint32_t addr) {
    asm volatile("ldmatrix.sync.aligned.m8n8.x4.trans.shared.b16 {%0,%1,%2,%3}, [%4];"
                 : "=r"(r[0]), "=r"(r[1]), "=r"(r[2]), "=r"(r[3]) : "r"(addr));
}
__device__ __forceinline__ void mma_f16(float* c, const uint32_t* a,
                                        const uint32_t* b) {
    asm volatile(
        "mma.sync.aligned.m16n8k16.row.col.f32.f16.f16.f32 "
        "{%0,%1,%2,%3}, {%4,%5,%6,%7}, {%8,%9}, {%0,%1,%2,%3};"
        : "+f"(c[0]), "+f"(c[1]), "+f"(c[2]), "+f"(c[3])
        : "r"(a[0]), "r"(a[1]), "r"(a[2]), "r"(a[3]), "r"(b[0]), "r"(b[1]));
}
__device__ __forceinline__ void cpa16(uint32_t dst, const void* src) {
    asm volatile("cp.async.cg.shared.global [%0], [%1], 16;"
                 :: "r"(dst), "l"(src));
}

// ---------------------------------------------------------------------------
// Tensor-core GEMM (NT): BM=128, BN=128, BK=32, 256 threads (8 warps),
// warp tile 32x64. NPROD=3: 2-stage; NPROD=2: 3-stage. (frozen from R15)
// ---------------------------------------------------------------------------
#define GBM 128
#define GBN 128
#define GBKT 32
#define ROWB    80
#define APL_B   (128 * ROWB)
#define BPL_B   (128 * ROWB)

template<int NPROD>
__global__ __launch_bounds__(256) void gemm_tc(
    const __half* __restrict__ Ah, const __half* __restrict__ Al,
    const __half* __restrict__ Bh, const __half* __restrict__ Bl,
    float* __restrict__ C, int n0, int N, int K, float cscale)
{
    constexpr int STAGE_B = (NPROD == 3) ? (2 * APL_B + 2 * BPL_B)
                                         : (2 * APL_B + BPL_B);
    constexpr int NSTAGE  = (NPROD == 3) ? 2 : 3;

    extern __shared__ char smg[];
    const uint32_t sb = smem_u32(smg);
    const int tid  = threadIdx.x;
    const int lane = tid & 31;
    const int w    = tid >> 5;
    const int wm   = (w & 3) * 32;
    const int wn   = (w >> 2) * 64;
    const int bn0  = blockIdx.x * GBN + n0;
    const int bm0  = blockIdx.y * GBM;
    const int niter = K / GBKT;

    auto load_stage = [&](int kt, int s) {
        const int NCH = (NPROD == 3) ? 8 : 6;
#pragma unroll
        for (int i = 0; i < NCH; i++) {
            int q = tid + i * 256;
            uint32_t dst;
            const __half* sp;
            if (q < 1024) {
                int pl = q >> 9;
                int r  = q & 511;
                int row = r >> 2, slot = r & 3;
                sp = (pl ? Al : Ah) + (size_t)(bm0 + row) * K
                   + kt * GBKT + slot * 8;
                dst = sb + s * STAGE_B + pl * APL_B + row * ROWB + slot * 16;
            } else {
                int qb = q - 1024;
                int pl = (NPROD == 3) ? (qb >> 9) : 0;
                int r  = qb & 511;
                int row = r >> 2, slot = r & 3;
                sp = (pl ? Bl : Bh) + (size_t)(bn0 + row) * K
                   + kt * GBKT + slot * 8;
                dst = sb + s * STAGE_B + 2 * APL_B + pl * BPL_B
                    + row * ROWB + slot * 16;
            }
            cpa16(dst, sp);
        }
    };

    float acc[2][8][4];
#pragma unroll
    for (int mt = 0; mt < 2; mt++)
#pragma unroll
        for (int nt = 0; nt < 8; nt++)
#pragma unroll
            for (int e = 0; e < 4; e++) acc[mt][nt][e] = 0.f;

#pragma unroll
    for (int s = 0; s < NSTAGE - 1; s++) {
        load_stage(s, s);
        asm volatile("cp.async.commit_group;");
    }

    const int a_row  = lane & 15, a_half = (lane >> 4) * 8;
    const int b_row2 = (lane & 7) | ((lane >> 1) & 8);
    const int b_half = ((lane >> 3) & 1) * 8;

    int cs = 0, ls = NSTAGE - 1;
    for (int kt = 0; kt < niter; kt++) {
        asm volatile("cp.async.wait_group %0;" :: "n"(NSTAGE - 2));
        __syncthreads();

        if (kt + NSTAGE - 1 < niter)
            load_stage(kt + NSTAGE - 1, ls);
        asm volatile("cp.async.commit_group;");
        if (++ls == NSTAGE) ls = 0;

        const uint32_t sbase = sb + cs * STAGE_B;
        if (++cs == NSTAGE) cs = 0;
#pragma unroll
        for (int ks = 0; ks < GBKT; ks += 16) {
            uint32_t ah[2][4], al[2][4];
#pragma unroll
            for (int mt = 0; mt < 2; mt++) {
                uint32_t aaddr = sbase + (wm + mt * 16 + a_row) * ROWB
                               + (ks + a_half) * 2;
                ldsm_x4(ah[mt], aaddr);
                ldsm_x4(al[mt], aaddr + APL_B);
            }
#pragma unroll
            for (int p = 0; p < 4; p++) {
                uint32_t baddr = sbase + 2 * APL_B
                               + (wn + p * 16 + b_row2) * ROWB
                               + (ks + b_half) * 2;
                uint32_t bh4[4], bl4[4];
                ldsm_x4(bh4, baddr);
                if (NPROD == 3) ldsm_x4(bl4, baddr + BPL_B);
#pragma unroll
                for (int j = 0; j < 2; j++) {
                    int nt = p * 2 + j;
#pragma unroll
                    for (int mt = 0; mt < 2; mt++) {
                        mma_f16(acc[mt][nt], ah[mt], &bh4[2 * j]);
                        if (NPROD == 3)
                            mma_f16(acc[mt][nt], ah[mt], &bl4[2 * j]);
                        mma_f16(acc[mt][nt], al[mt], &bh4[2 * j]);
                    }
                }
            }
        }
        __syncthreads();
    }

    const int cr = lane >> 2, cc = (lane & 3) * 2;
#pragma unroll
    for (int mt = 0; mt < 2; mt++) {
#pragma unroll
        for (int nt = 0; nt < 8; nt++) {
            int row0 = bm0 + wm + mt * 16 + cr;
            int col  = bn0 + wn + nt * 8 + cc;
            *(float2*)&C[(size_t)row0 * N + col] =
                make_float2(acc[mt][nt][0] * cscale, acc[mt][nt][1] * cscale);
            *(float2*)&C[(size_t)(row0 + 8) * N + col] =
                make_float2(acc[mt][nt][2] * cscale, acc[mt][nt][3] * cscale);
        }
    }
}

#define GEMM_SMEM3 (2 * (2 * APL_B + 2 * BPL_B))
#define GEMM_SMEM2 (3 * (2 * APL_B + BPL_B))

// ---------------------------------------------------------------------------
// Prep: RoPE (q,k) / copy (v) -> fp16 planes [head][t][d]. V: hi only.
// ---------------------------------------------------------------------------
__global__ __launch_bounds__(256) void prep_qkv(
    const float* __restrict__ cosb, const float* __restrict__ sinb)
{
    const int hh = blockIdx.y;
    const int t  = blockIdx.x * 8 + (threadIdx.x >> 5);
    const int lane = threadIdx.x & 31;
    const int d0 = lane * 4;
    const float* row = g_qkv + (size_t)t * QKVW + hh * HD;

    float x1[4], x2[4], o1[4], o2[4];
    *(float4*)x1 = *(const float4*)(row + d0);
    *(float4*)x2 = *(const float4*)(row + d0 + 128);
    const bool isv = (hh >= NH + NKV);
    if (!isv) {
        float c[4], s[4];
        *(float4*)c = *(const float4*)(cosb + (size_t)t * 128 + d0);
        *(float4*)s = *(const float4*)(sinb + (size_t)t * 128 + d0);
#pragma unroll
        for (int i = 0; i < 4; i++) {
            o1[i] = x1[i] * c[i] - x2[i] * s[i];
            o2[i] = x2[i] * c[i] + x1[i] * s[i];
        }
    } else {
#pragma unroll
        for (int i = 0; i < 4; i++) { o1[i] = x1[i]; o2[i] = x2[i]; }
    }

    if (isv) {
        __half* dh = g_vh + ((size_t)(hh - NH - NKV) * TT + t) * HD;
#pragma unroll
        for (int i = 0; i < 4; i += 2) {
            *(__half2*)(dh + d0 + i) = __halves2half2(
                __float2half(o1[i]), __float2half(o1[i + 1]));
            *(__half2*)(dh + d0 + 128 + i) = __halves2half2(
                __float2half(o2[i]), __float2half(o2[i + 1]));
        }
        return;
    }

    __half *dh, *dl;
    if (hh < NH) { dh = g_qh + ((size_t)hh * TT + t) * HD;
                   dl = g_ql + ((size_t)hh * TT + t) * HD; }
    else         { dh = g_kh + ((size_t)(hh - NH) * TT + t) * HD;
                   dl = g_kl + ((size_t)(hh - NH) * TT + t) * HD; }

#pragma unroll
    for (int i = 0; i < 4; i += 2) {
        __half h0 = __float2half(o1[i]),   h1 = __float2half(o1[i+1]);
        __half g0 = __float2half(o2[i]),   g1 = __float2half(o2[i+1]);
        *(__half2*)(dh + d0 + i)       = __halves2half2(h0, h1);
        *(__half2*)(dh + d0 + 128 + i) = __halves2half2(g0, g1);
        *(__half2*)(dl + d0 + i) = __halves2half2(
            __float2half(o1[i]   - __half2float(h0)),
            __float2half(o1[i+1] - __half2float(h1)));
        *(__half2*)(dl + d0 + 128 + i) = __halves2half2(
            __float2half(o2[i]   - __half2float(g0)),
            __float2half(o2[i+1] - __half2float(g1)));
    }
}

// ---------------------------------------------------------------------------
// Tensor-core flash attention. 256 thr, Bq=Bk=64, D=256.
// S: 3-product fp16; softmax fp32; PV: 1-product. Double-buffered V,
// staged cp.async waits: K hidden under B+C+A, V hidden under A+B.
// ---------------------------------------------------------------------------
#define DPAD 264
#define STLD 68
#define PTLD 72
#define ATT_SMEM_BYTES (6*64*DPAD*2 + 64*STLD*4 + 64*PTLD*2 + 64*3*4)

__global__ __launch_bounds__(256) void attn_kernel(
    __half* __restrict__ outH, __half* __restrict__ outL)
{
    extern __shared__ __half smh[];
    __half* Qh = smh;
    __half* Ql = Qh + 64 * DPAD;
    __half* Kh = Ql + 64 * DPAD;
    __half* Kl = Kh + 64 * DPAD;
    __half* Vb0 = Kl + 64 * DPAD;         // V buffer 0
    __half* Vb1 = Vb0 + 64 * DPAD;        // V buffer 1
    float*  St = (float*)(Vb1 + 64 * DPAD);
    __half* Pt = (__half*)(St + 64 * STLD);
    float* rowm = (float*)(Pt + 64 * PTLD);
    float* rowl = rowm + 64;
    float* alf  = rowl + 64;

    const int tid  = threadIdx.x;
    const int lane = tid & 31, w = tid >> 5;
    const int qt   = blockIdx.x, h = blockIdx.y, b = blockIdx.z;
    const int qi0  = qt * BQ;
    const int tok0 = b * SEQ;
    const int kh   = h >> 1;

    const uint32_t sQh = smem_u32(Qh), sQl = smem_u32(Ql);
    const uint32_t sKh = smem_u32(Kh), sKl = smem_u32(Kl);
    const uint32_t sV[2] = { smem_u32(Vb0), smem_u32(Vb1) };
    const uint32_t sPt = smem_u32(Pt);

    const __half* kbaseH = g_kh + ((size_t)kh * TT + tok0) * HD;
    const __half* kbaseL = g_kl + ((size_t)kh * TT + tok0) * HD;
    const __half* vbaseH = g_vh + ((size_t)kh * TT + tok0) * HD;

    auto load_k = [&](int kj0) {
#pragma unroll
        for (int i = 0; i < 16; i++) {
            int q = tid + i * 256;
            int pl = q >> 11, r = q & 2047;
            int row = r >> 5, slot = r & 31;
            const __half* sp = (pl ? kbaseL : kbaseH)
                             + (size_t)(kj0 + row) * HD + slot * 8;
            cpa16((pl ? sKl : sKh) + row * DPAD * 2 + slot * 16, sp);
        }
    };
    auto load_v = [&](int kj0, int buf) {
#pragma unroll
        for (int i = 0; i < 8; i++) {
            int q = tid + i * 256;
            int row = q >> 5, slot = q & 31;
            const __half* sp = vbaseH + (size_t)(kj0 + row) * HD + slot * 8;
            cpa16(sV[buf] + row * DPAD * 2 + slot * 16, sp);
        }
    };

    const int kt0 = (qi0 - WIN > 0) ? (qi0 - WIN) : 0;

    // prologue: group1 = Q + K(first), group2 = V(first, buf 0)
    {
        const __half* qH = g_qh + ((size_t)h * TT + tok0 + qi0) * HD;
        const __half* qL = g_ql + ((size_t)h * TT + tok0 + qi0) * HD;
#pragma unroll
        for (int i = 0; i < 16; i++) {
            int q = tid + i * 256;
            int pl = q >> 11, r = q & 2047;
            int row = r >> 5, slot = r & 31;
            const __half* sp = (pl ? qL : qH) + (size_t)row * HD + slot * 8;
            cpa16((pl ? sQl : sQh) + row * DPAD * 2 + slot * 16, sp);
        }
        load_k(kt0);
        asm volatile("cp.async.commit_group;");
        load_v(kt0, 0);
        asm volatile("cp.async.commit_group;");
    }
    if (tid < 64) { rowm[tid] = -1e30f; rowl[tid] = 0.f; }

    const int wr  = (w & 3) * 16;
    const int wc  = (w >> 2) * 32;
    const int wc2 = (w >> 2) * 128;
    const int a_row  = lane & 15, a_half = (lane >> 4) * 8;
    const int b_row2 = (lane & 7) | ((lane >> 1) & 8);
    const int b_half = ((lane >> 3) & 1) * 8;
    const int c_row  = lane >> 2, c_col = (lane & 3) * 2;

    float o[16][4];
#pragma unroll
    for (int nf = 0; nf < 16; nf++)
#pragma unroll
        for (int e = 0; e < 4; e++) o[nf][e] = 0.f;

    int buf = 0;
    for (int kj0 = kt0; kj0 <= qi0; kj0 += BK, buf ^= 1) {
        const bool has_next = (kj0 + BK <= qi0);

        // K (and Q) guaranteed; V of this iter may still be in flight.
        asm volatile("cp.async.wait_group 1;");
        __syncthreads();

        // ---- Phase A: S = Q K^T (3-product) ----
        float s4[4][4];
#pragma unroll
        for (int nf = 0; nf < 4; nf++)
#pragma unroll
            for (int e = 0; e < 4; e++) s4[nf][e] = 0.f;

#pragma unroll
        for (int ks = 0; ks < HD; ks += 16) {
            uint32_t ah[4], al4[4];
            uint32_t aoff = ((wr + a_row) * DPAD + ks + a_half) * 2;
            ldsm_x4(ah,  sQh + aoff);
            ldsm_x4(al4, sQl + aoff);
#pragma unroll
            for (int p = 0; p < 2; p++) {
                uint32_t boff = ((wc + p * 16 + b_row2) * DPAD + ks + b_half) * 2;
                uint32_t kbh[4], kbl[4];
                ldsm_x4(kbh, sKh + boff);
                ldsm_x4(kbl, sKl + boff);
#pragma unroll
                for (int j = 0; j < 2; j++) {
                    int nf = p * 2 + j;
                    mma_f16(s4[nf], ah,  &kbh[2 * j]);
                    mma_f16(s4[nf], ah,  &kbl[2 * j]);
                    mma_f16(s4[nf], al4, &kbh[2 * j]);
                }
            }
        }
        const float cf = SCALE / SOFTCAP;
#pragma unroll
        for (int nf = 0; nf < 4; nf++) {
#pragma unroll
            for (int e = 0; e < 4; e++) {
                int ir = wr + c_row + ((e >> 1) * 8);
                int jc = wc + nf * 8 + c_col + (e & 1);
                float sv = SOFTCAP * tanhf(s4[nf][e] * cf);
                int ig = qi0 + ir, jg = kj0 + jc;
                if (jg > ig || jg < ig - WIN) sv = -1e30f;
                St[ir * STLD + jc] = sv;
            }
        }
        __syncthreads();   // St ready; all warps done reading K

        // issue next K (group) then next V (group) into the other buffer
        if (has_next) {
            load_k(kj0 + BK);
            asm volatile("cp.async.commit_group;");
            load_v(kj0 + BK, buf ^ 1);
            asm volatile("cp.async.commit_group;");
        }

        // ---- Phase B: softmax ----
        {
            int qr = tid >> 2, sub = tid & 3;
            float mx = -1e30f;
#pragma unroll
            for (int ii = 0; ii < 16; ii++)
                mx = fmaxf(mx, St[qr * STLD + sub * 16 + ii]);
            mx = fmaxf(mx, __shfl_xor_sync(0xffffffffu, mx, 1));
            mx = fmaxf(mx, __shfl_xor_sync(0xffffffffu, mx, 2));
            float mold = rowm[qr];
            float mnew = fmaxf(mold, mx);
            float al   = __expf(mold - mnew);
            float ps   = 0.f;
#pragma unroll
            for (int ii = 0; ii < 16; ii++) {
                float sv = St[qr * STLD + sub * 16 + ii];
                float p  = (sv > -1e29f) ? __expf(sv - mnew) : 0.f;
                __half ph = __float2half(p);
                Pt[qr * PTLD + sub * 16 + ii] = ph;
                ps += __half2float(ph);
            }
            ps += __shfl_xor_sync(0xffffffffu, ps, 1);
            ps += __shfl_xor_sync(0xffffffffu, ps, 2);
            if (sub == 0) {
                rowm[qr] = mnew;
                rowl[qr] = rowl[qr] * al + ps;
                alf[qr]  = al;
            }
        }

        // V(cur) done; next K/V (2 groups) may still be pending.
        if (has_next) { asm volatile("cp.async.wait_group 2;"); }
        else          { asm volatile("cp.async.wait_group 0;"); }
        __syncthreads();   // Pt ready + V(cur) visible to all

        // ---- Phase C: O = diag(alpha) O + P Vh ----
        {
            float a1 = alf[wr + c_row], a2 = alf[wr + c_row + 8];
#pragma unroll
            for (int nf = 0; nf < 16; nf++) {
                o[nf][0] *= a1; o[nf][1] *= a1;
                o[nf][2] *= a2; o[nf][3] *= a2;
            }
            const uint32_t sVc = sV[buf];
#pragma unroll
            for (int kk = 0; kk < BK; kk += 16) {
                uint32_t pf[4];
                ldsm_x4(pf, sPt + ((wr + a_row) * PTLD + kk + a_half) * 2);
#pragma unroll
                for (int dn = 0; dn < 8; dn++) {
                    int d0 = wc2 + dn * 16;
                    uint32_t voff = ((kk + (lane & 15)) * DPAD
                                   + d0 + (lane >> 4) * 8) * 2;
                    uint32_t vbh[4];
                    ldsm_x4t(vbh, sVc + voff);
                    mma_f16(o[dn * 2],     pf, &vbh[0]);
                    mma_f16(o[dn * 2 + 1], pf, &vbh[2]);
                }
            }
        }
    }

    // ---- epilogue: normalize, split to fp16 hi/lo, store ----
    {
        int r1 = wr + c_row;
        float i1 = 1.0f / rowl[r1], i2 = 1.0f / rowl[r1 + 8];
        size_t t1 = (size_t)(tok0 + qi0 + r1);
#pragma unroll
        for (int nf = 0; nf < 16; nf++) {
            int col = h * HD + wc2 + nf * 8 + c_col;
            float v0 = o[nf][0] * i1, v1 = o[nf][1] * i1;
            float v2 = o[nf][2] * i2, v3 = o[nf][3] * i2;
            __half h0 = __float2half(v0), h1 = __float2half(v1);
            __half h2 = __float2half(v2), h3 = __float2half(v3);
            *(__half2*)(outH + t1 * ATTW + col) = __halves2half2(h0, h1);
            *(__half2*)(outH + (t1 + 8) * ATTW + col) = __halves2half2(h2, h3);
            *(__half2*)(outL + t1 * ATTW + col) = __halves2half2(
                __float2half(v0 - __half2float(h0)),
                __float2half(v1 - __half2float(h1)));
            *(__half2*)(outL + (t1 + 8) * ATTW + col) = __halves2half2(
                __float2half(v2 - __half2float(h2)),
                __float2half(v3 - __half2float(h3)));
        }
    }
}

// ---------------------------------------------------------------------------
extern "C" void kernel_launch(void* const* d_in, const int* in_sizes, int n_in,
                              void* d_out, int out_size)
{
    const float* hidden = (const float*)d_in[0];
    const float* cosb   = (const float*)d_in[1];
    const float* sinb   = (const float*)d_in[2];
    const float* w_qkv  = (const float*)d_in[3];
    const float* w_o    = (const float*)d_in[4];
    float* out = (float*)d_out;

    float* d_qkv;
    cudaGetSymbolAddress((void**)&d_qkv, g_qkv);
    __half *hH, *hL, *wqH, *wqL, *aH, *aL, *woH, *woL;
    cudaGetSymbolAddress((void**)&hH,  g_hidH);
    cudaGetSymbolAddress((void**)&hL,  g_hidL);
    cudaGetSymbolAddress((void**)&wqH, g_wqH);
    cudaGetSymbolAddress((void**)&wqL, g_wqL);
    cudaGetSymbolAddress((void**)&aH,  g_aH);
    cudaGetSymbolAddress((void**)&aL,  g_aL);
    cudaGetSymbolAddress((void**)&woH, g_woH);
    cudaGetSymbolAddress((void**)&woL, g_woL);

    cudaFuncSetAttribute(gemm_tc<3>, cudaFuncAttributeMaxDynamicSharedMemorySize,
                         GEMM_SMEM3);
    cudaFuncSetAttribute(gemm_tc<2>, cudaFuncAttributeMaxDynamicSharedMemorySize,
                         GEMM_SMEM2);
    cudaFuncSetAttribute(attn_kernel, cudaFuncAttributeMaxDynamicSharedMemorySize,
                         ATT_SMEM_BYTES);

    // 0. split inputs for GEMM1
    {
        size_t n1 = (size_t)TT * HIDDIM;
        size_t n2 = (size_t)QKVW * HIDDIM;
        split_f16<<<(unsigned)((n1 / 4 + 255) / 256), 256>>>(hidden, hH, hL, 1.0f, n1);
        split_f16<<<(unsigned)((n2 / 4 + 255) / 256), 256>>>(w_qkv, wqH, wqL, WSCALE, n2);
    }

    // 1. QKV projection: Q+K columns (3-product), V columns (2-product)
    gemm_tc<3><<<dim3(6144 / GBN, TT / GBM), 256, GEMM_SMEM3>>>(
        hH, hL, wqH, wqL, d_qkv, 0, QKVW, HIDDIM, CSCALE);
    gemm_tc<2><<<dim3(2048 / GBN, TT / GBM), 256, GEMM_SMEM2>>>(
        hH, hL, wqH, wqL, d_qkv, 6144, QKVW, HIDDIM, CSCALE);

    // 2. RoPE + fp16 prep of Q/K (hi/lo) and V (hi) planes
    prep_qkv<<<dim3(TT / 8, NH + 2 * NKV), 256>>>(cosb, sinb);

    // 3. Tensor-core sliding-window attention (writes aH/aL directly)
    attn_kernel<<<dim3(SEQ / BQ, NH, NB), 256, ATT_SMEM_BYTES>>>(aH, aL);

    // 4. split w_o only
    {
        size_t n4 = (size_t)HIDDIM * ATTW;
        split_f16<<<(unsigned)((n4 / 4 + 255) / 256), 256>>>(w_o, woH, woL, WSCALE, n4);
    }

    // 5. Output projection (2-product)
    gemm_tc<2><<<dim3(HIDDIM / GBN, TT / GBM), 256, GEMM_SMEM2>>>(
        aH, aL, woH, woL, out, 0, HIDDIM, ATTW, CSCALE);
}

// round 17
// speedup vs baseline: 1.2244x; 1.2244x over previous
#include <cuda_runtime.h>
#include <cuda_fp16.h>
#include <math.h>
#include <stdint.h>

#define TT     4096      // total tokens B*S
#define HIDDIM 3584
#define NH     16
#define NKV    8
#define HD     256
#define SEQ    2048
#define NB     2
#define QKVW   8192      // (NH + 2*NKV) * HD
#define ATTW   4096      // NH * HD
#define WIN    1024
#define SCALE  0.0625f   // 256^-0.5
#define SOFTCAP 50.0f

#define BQ 64
#define BK 64

#define WSCALE 32.0f
#define CSCALE (1.0f / 32.0f)

// ---------------- scratch (static device allocations) ----------------------
__device__ float g_qkv[(size_t)TT * QKVW];

// fp16 attention operand planes, layout [head][t][d]
__device__ __half g_qh[(size_t)NH * TT * HD];
__device__ __half g_ql[(size_t)NH * TT * HD];
__device__ __half g_kh[(size_t)NKV * TT * HD];
__device__ __half g_kl[(size_t)NKV * TT * HD];
__device__ __half g_vh[(size_t)NKV * TT * HD];

// fp16 split planes for projections
__device__ __half g_hidH[(size_t)TT * HIDDIM];
__device__ __half g_hidL[(size_t)TT * HIDDIM];
__device__ __half g_wqH[(size_t)QKVW * HIDDIM];
__device__ __half g_aH[(size_t)TT * ATTW];
__device__ __half g_aL[(size_t)TT * ATTW];
__device__ __half g_woH[(size_t)HIDDIM * ATTW];

// ---------------------------------------------------------------------------
// fp32 -> fp16 hi/lo split (with pre-scale)
// ---------------------------------------------------------------------------
__global__ __launch_bounds__(256) void split_f16(
    const float* __restrict__ src,
    __half* __restrict__ hi, __half* __restrict__ lo, float scale, size_t n)
{
    size_t i = ((size_t)blockIdx.x * blockDim.x + threadIdx.x) * 4;
    if (i >= n) return;
    float4 v = *(const float4*)(src + i);
    v.x *= scale; v.y *= scale; v.z *= scale; v.w *= scale;
    __half h0 = __float2half(v.x), h1 = __float2half(v.y);
    __half h2 = __float2half(v.z), h3 = __float2half(v.w);
    __half l0 = __float2half(v.x - __half2float(h0));
    __half l1 = __float2half(v.y - __half2float(h1));
    __half l2 = __float2half(v.z - __half2float(h2));
    __half l3 = __float2half(v.w - __half2float(h3));
    *(__half2*)(hi + i)     = __halves2half2(h0, h1);
    *(__half2*)(hi + i + 2) = __halves2half2(h2, h3);
    *(__half2*)(lo + i)     = __halves2half2(l0, l1);
    *(__half2*)(lo + i + 2) = __halves2half2(l2, l3);
}

// fp32 -> fp16 hi only (for weights whose lo plane is never used)
__global__ __launch_bounds__(256) void cvt_f16(
    const float* __restrict__ src, __half* __restrict__ hi, float scale, size_t n)
{
    size_t i = ((size_t)blockIdx.x * blockDim.x + threadIdx.x) * 4;
    if (i >= n) return;
    float4 v = *(const float4*)(src + i);
    *(__half2*)(hi + i)     = __halves2half2(__float2half(v.x * scale),
                                             __float2half(v.y * scale));
    *(__half2*)(hi + i + 2) = __halves2half2(__float2half(v.z * scale),
                                             __float2half(v.w * scale));
}

// ---------------------------------------------------------------------------
// helpers
// ---------------------------------------------------------------------------
__device__ __forceinline__ uint32_t smem_u32(const void* p) {
    uint32_t a;
    asm("{ .reg .u64 t; cvta.to.shared.u64 t, %1; cvt.u32.u64 %0, t; }"
        : "=r"(a) : "l"(p));
    return a;
}
__device__ __forceinline__ void ldsm_x4(uint32_t* r, uint32_t addr) {
    asm volatile("ldmatrix.sync.aligned.m8n8.x4.shared.b16 {%0,%1,%2,%3}, [%4];"
                 : "=r"(r[0]), "=r"(r[1]), "=r"(r[2]), "=r"(r[3]) : "r"(addr));
}
__device__ __forceinline__ void ldsm_x4t(uint32_t* r, uint32_t addr) {
    asm volatile("ldmatrix.sync.aligned.m8n8.x4.trans.shared.b16 {%0,%1,%2,%3}, [%4];"
                 : "=r"(r[0]), "=r"(r[1]), "=r"(r[2]), "=r"(r[3]) : "r"(addr));
}
__device__ __forceinline__ void mma_f16(float* c, const uint32_t* a,
                                        const uint32_t* b) {
    asm volatile(
        "mma.sync.aligned.m16n8k16.row.col.f32.f16.f16.f32 "
        "{%0,%1,%2,%3}, {%4,%5,%6,%7}, {%8,%9}, {%0,%1,%2,%3};"
        : "+f"(c[0]), "+f"(c[1]), "+f"(c[2]), "+f"(c[3])
        : "r"(a[0]), "r"(a[1]), "r"(a[2]), "r"(a[3]), "r"(b[0]), "r"(b[1]));
}
__device__ __forceinline__ void cpa16(uint32_t dst, const void* src) {
    asm volatile("cp.async.cg.shared.global [%0], [%1], 16;"
                 :: "r"(dst), "l"(src));
}

// ---------------------------------------------------------------------------
// Tensor-core GEMM (NT): BM=128, BN=128, BK=32, 256 threads (8 warps),
// warp tile 32x64. NPROD=2: AhBh + AlBh, 3-stage. (inner loop frozen)
// ---------------------------------------------------------------------------
#define GBM 128
#define GBN 128
#define GBKT 32
#define ROWB    80
#define APL_B   (128 * ROWB)
#define BPL_B   (128 * ROWB)

template<int NPROD>
__global__ __launch_bounds__(256) void gemm_tc(
    const __half* __restrict__ Ah, const __half* __restrict__ Al,
    const __half* __restrict__ Bh, const __half* __restrict__ Bl,
    float* __restrict__ C, int n0, int N, int K, float cscale)
{
    constexpr int STAGE_B = (NPROD == 3) ? (2 * APL_B + 2 * BPL_B)
                                         : (2 * APL_B + BPL_B);
    constexpr int NSTAGE  = (NPROD == 3) ? 2 : 3;

    extern __shared__ char smg[];
    const uint32_t sb = smem_u32(smg);
    const int tid  = threadIdx.x;
    const int lane = tid & 31;
    const int w    = tid >> 5;
    const int wm   = (w & 3) * 32;
    const int wn   = (w >> 2) * 64;
    const int bn0  = blockIdx.x * GBN + n0;
    const int bm0  = blockIdx.y * GBM;
    const int niter = K / GBKT;

    auto load_stage = [&](int kt, int s) {
        const int NCH = (NPROD == 3) ? 8 : 6;
#pragma unroll
        for (int i = 0; i < NCH; i++) {
            int q = tid + i * 256;
            uint32_t dst;
            const __half* sp;
            if (q < 1024) {
                int pl = q >> 9;
                int r  = q & 511;
                int row = r >> 2, slot = r & 3;
                sp = (pl ? Al : Ah) + (size_t)(bm0 + row) * K
                   + kt * GBKT + slot * 8;
                dst = sb + s * STAGE_B + pl * APL_B + row * ROWB + slot * 16;
            } else {
                int qb = q - 1024;
                int pl = (NPROD == 3) ? (qb >> 9) : 0;
                int r  = qb & 511;
                int row = r >> 2, slot = r & 3;
                sp = (pl ? Bl : Bh) + (size_t)(bn0 + row) * K
                   + kt * GBKT + slot * 8;
                dst = sb + s * STAGE_B + 2 * APL_B + pl * BPL_B
                    + row * ROWB + slot * 16;
            }
            cpa16(dst, sp);
        }
    };

    float acc[2][8][4];
#pragma unroll
    for (int mt = 0; mt < 2; mt++)
#pragma unroll
        for (int nt = 0; nt < 8; nt++)
#pragma unroll
            for (int e = 0; e < 4; e++) acc[mt][nt][e] = 0.f;

#pragma unroll
    for (int s = 0; s < NSTAGE - 1; s++) {
        load_stage(s, s);
        asm volatile("cp.async.commit_group;");
    }

    const int a_row  = lane & 15, a_half = (lane >> 4) * 8;
    const int b_row2 = (lane & 7) | ((lane >> 1) & 8);
    const int b_half = ((lane >> 3) & 1) * 8;

    int cs = 0, ls = NSTAGE - 1;
    for (int kt = 0; kt < niter; kt++) {
        asm volatile("cp.async.wait_group %0;" :: "n"(NSTAGE - 2));
        __syncthreads();

        if (kt + NSTAGE - 1 < niter)
            load_stage(kt + NSTAGE - 1, ls);
        asm volatile("cp.async.commit_group;");
        if (++ls == NSTAGE) ls = 0;

        const uint32_t sbase = sb + cs * STAGE_B;
        if (++cs == NSTAGE) cs = 0;
#pragma unroll
        for (int ks = 0; ks < GBKT; ks += 16) {
            uint32_t ah[2][4], al[2][4];
#pragma unroll
            for (int mt = 0; mt < 2; mt++) {
                uint32_t aaddr = sbase + (wm + mt * 16 + a_row) * ROWB
                               + (ks + a_half) * 2;
                ldsm_x4(ah[mt], aaddr);
                ldsm_x4(al[mt], aaddr + APL_B);
            }
#pragma unroll
            for (int p = 0; p < 4; p++) {
                uint32_t baddr = sbase + 2 * APL_B
                               + (wn + p * 16 + b_row2) * ROWB
                               + (ks + b_half) * 2;
                uint32_t bh4[4], bl4[4];
                ldsm_x4(bh4, baddr);
                if (NPROD == 3) ldsm_x4(bl4, baddr + BPL_B);
#pragma unroll
                for (int j = 0; j < 2; j++) {
                    int nt = p * 2 + j;
#pragma unroll
                    for (int mt = 0; mt < 2; mt++) {
                        mma_f16(acc[mt][nt], ah[mt], &bh4[2 * j]);
                        if (NPROD == 3)
                            mma_f16(acc[mt][nt], ah[mt], &bl4[2 * j]);
                        mma_f16(acc[mt][nt], al[mt], &bh4[2 * j]);
                    }
                }
            }
        }
        __syncthreads();
    }

    const int cr = lane >> 2, cc = (lane & 3) * 2;
#pragma unroll
    for (int mt = 0; mt < 2; mt++) {
#pragma unroll
        for (int nt = 0; nt < 8; nt++) {
            int row0 = bm0 + wm + mt * 16 + cr;
            int col  = bn0 + wn + nt * 8 + cc;
            *(float2*)&C[(size_t)row0 * N + col] =
                make_float2(acc[mt][nt][0] * cscale, acc[mt][nt][1] * cscale);
            *(float2*)&C[(size_t)(row0 + 8) * N + col] =
                make_float2(acc[mt][nt][2] * cscale, acc[mt][nt][3] * cscale);
        }
    }
}

#define GEMM_SMEM2 (3 * (2 * APL_B + BPL_B))

// ---------------------------------------------------------------------------
// Prep: RoPE (q,k) / copy (v) -> fp16 planes [head][t][d]. V: hi only.
// ---------------------------------------------------------------------------
__global__ __launch_bounds__(256) void prep_qkv(
    const float* __restrict__ cosb, const float* __restrict__ sinb)
{
    const int hh = blockIdx.y;
    const int t  = blockIdx.x * 8 + (threadIdx.x >> 5);
    const int lane = threadIdx.x & 31;
    const int d0 = lane * 4;
    const float* row = g_qkv + (size_t)t * QKVW + hh * HD;

    float x1[4], x2[4], o1[4], o2[4];
    *(float4*)x1 = *(const float4*)(row + d0);
    *(float4*)x2 = *(const float4*)(row + d0 + 128);
    const bool isv = (hh >= NH + NKV);
    if (!isv) {
        float c[4], s[4];
        *(float4*)c = *(const float4*)(cosb + (size_t)t * 128 + d0);
        *(float4*)s = *(const float4*)(sinb + (size_t)t * 128 + d0);
#pragma unroll
        for (int i = 0; i < 4; i++) {
            o1[i] = x1[i] * c[i] - x2[i] * s[i];
            o2[i] = x2[i] * c[i] + x1[i] * s[i];
        }
    } else {
#pragma unroll
        for (int i = 0; i < 4; i++) { o1[i] = x1[i]; o2[i] = x2[i]; }
    }

    if (isv) {
        __half* dh = g_vh + ((size_t)(hh - NH - NKV) * TT + t) * HD;
#pragma unroll
        for (int i = 0; i < 4; i += 2) {
            *(__half2*)(dh + d0 + i) = __halves2half2(
                __float2half(o1[i]), __float2half(o1[i + 1]));
            *(__half2*)(dh + d0 + 128 + i) = __halves2half2(
                __float2half(o2[i]), __float2half(o2[i + 1]));
        }
        return;
    }

    __half *dh, *dl;
    if (hh < NH) { dh = g_qh + ((size_t)hh * TT + t) * HD;
                   dl = g_ql + ((size_t)hh * TT + t) * HD; }
    else         { dh = g_kh + ((size_t)(hh - NH) * TT + t) * HD;
                   dl = g_kl + ((size_t)(hh - NH) * TT + t) * HD; }

#pragma unroll
    for (int i = 0; i < 4; i += 2) {
        __half h0 = __float2half(o1[i]),   h1 = __float2half(o1[i+1]);
        __half g0 = __float2half(o2[i]),   g1 = __float2half(o2[i+1]);
        *(__half2*)(dh + d0 + i)       = __halves2half2(h0, h1);
        *(__half2*)(dh + d0 + 128 + i) = __halves2half2(g0, g1);
        *(__half2*)(dl + d0 + i) = __halves2half2(
            __float2half(o1[i]   - __half2float(h0)),
            __float2half(o1[i+1] - __half2float(h1)));
        *(__half2*)(dl + d0 + 128 + i) = __halves2half2(
            __float2half(o2[i]   - __half2float(g0)),
            __float2half(o2[i+1] - __half2float(g1)));
    }
}

// ---------------------------------------------------------------------------
// Tensor-core flash attention (R15 structure). 256 thr, Bq=Bk=64, D=256.
// S: 3-product fp16; softmax fp32; PV: 1-product.
// ---------------------------------------------------------------------------
#define DPAD 264
#define STLD 68
#define PTLD 72
#define ATT_SMEM_BYTES (5*64*DPAD*2 + 64*STLD*4 + 64*PTLD*2 + 64*3*4)

__global__ __launch_bounds__(256) void attn_kernel(
    __half* __restrict__ outH, __half* __restrict__ outL)
{
    extern __shared__ __half smh[];
    __half* Qh = smh;
    __half* Ql = Qh + 64 * DPAD;
    __half* Kh = Ql + 64 * DPAD;
    __half* Kl = Kh + 64 * DPAD;
    __half* Vh = Kl + 64 * DPAD;
    float*  St = (float*)(Vh + 64 * DPAD);
    __half* Pt = (__half*)(St + 64 * STLD);
    float* rowm = (float*)(Pt + 64 * PTLD);
    float* rowl = rowm + 64;
    float* alf  = rowl + 64;

    const int tid  = threadIdx.x;
    const int lane = tid & 31, w = tid >> 5;
    const int qt   = blockIdx.x, h = blockIdx.y, b = blockIdx.z;
    const int qi0  = qt * BQ;
    const int tok0 = b * SEQ;
    const int kh   = h >> 1;

    const uint32_t sQh = smem_u32(Qh), sQl = smem_u32(Ql);
    const uint32_t sKh = smem_u32(Kh), sKl = smem_u32(Kl);
    const uint32_t sVh = smem_u32(Vh);
    const uint32_t sPt = smem_u32(Pt);

    const __half* kbaseH = g_kh + ((size_t)kh * TT + tok0) * HD;
    const __half* kbaseL = g_kl + ((size_t)kh * TT + tok0) * HD;
    const __half* vbaseH = g_vh + ((size_t)kh * TT + tok0) * HD;

    auto load_k = [&](int kj0) {
#pragma unroll
        for (int i = 0; i < 16; i++) {
            int q = tid + i * 256;
            int pl = q >> 11, r = q & 2047;
            int row = r >> 5, slot = r & 31;
            const __half* sp = (pl ? kbaseL : kbaseH)
                             + (size_t)(kj0 + row) * HD + slot * 8;
            cpa16((pl ? sKl : sKh) + row * DPAD * 2 + slot * 16, sp);
        }
        asm volatile("cp.async.commit_group;");
    };
    auto load_v = [&](int kj0) {
#pragma unroll
        for (int i = 0; i < 8; i++) {
            int q = tid + i * 256;
            int row = q >> 5, slot = q & 31;
            const __half* sp = vbaseH + (size_t)(kj0 + row) * HD + slot * 8;
            cpa16(sVh + row * DPAD * 2 + slot * 16, sp);
        }
        asm volatile("cp.async.commit_group;");
    };

    // Q load (one-time)
    {
        const __half* qH = g_qh + ((size_t)h * TT + tok0 + qi0) * HD;
        const __half* qL = g_ql + ((size_t)h * TT + tok0 + qi0) * HD;
#pragma unroll
        for (int i = 0; i < 16; i++) {
            int q = tid + i * 256;
            int pl = q >> 11, r = q & 2047;
            int row = r >> 5, slot = r & 31;
            const __half* sp = (pl ? qL : qH) + (size_t)row * HD + slot * 8;
            cpa16((pl ? sQl : sQh) + row * DPAD * 2 + slot * 16, sp);
        }
        asm volatile("cp.async.commit_group;");
    }
    if (tid < 64) { rowm[tid] = -1e30f; rowl[tid] = 0.f; }

    const int wr  = (w & 3) * 16;
    const int wc  = (w >> 2) * 32;
    const int wc2 = (w >> 2) * 128;
    const int a_row  = lane & 15, a_half = (lane >> 4) * 8;
    const int b_row2 = (lane & 7) | ((lane >> 1) & 8);
    const int b_half = ((lane >> 3) & 1) * 8;
    const int c_row  = lane >> 2, c_col = (lane & 3) * 2;

    float o[16][4];
#pragma unroll
    for (int nf = 0; nf < 16; nf++)
#pragma unroll
        for (int e = 0; e < 4; e++) o[nf][e] = 0.f;

    const int kt0 = (qi0 - WIN > 0) ? (qi0 - WIN) : 0;
    load_k(kt0);
    load_v(kt0);

    for (int kj0 = kt0; kj0 <= qi0; kj0 += BK) {
        asm volatile("cp.async.wait_group 0;");
        __syncthreads();

        // ---- Phase A: S = Q K^T (3-product) ----
        float s4[4][4];
#pragma unroll
        for (int nf = 0; nf < 4; nf++)
#pragma unroll
            for (int e = 0; e < 4; e++) s4[nf][e] = 0.f;

#pragma unroll
        for (int ks = 0; ks < HD; ks += 16) {
            uint32_t ah[4], al4[4];
            uint32_t aoff = ((wr + a_row) * DPAD + ks + a_half) * 2;
            ldsm_x4(ah,  sQh + aoff);
            ldsm_x4(al4, sQl + aoff);
#pragma unroll
            for (int p = 0; p < 2; p++) {
                uint32_t boff = ((wc + p * 16 + b_row2) * DPAD + ks + b_half) * 2;
                uint32_t kbh[4], kbl[4];
                ldsm_x4(kbh, sKh + boff);
                ldsm_x4(kbl, sKl + boff);
#pragma unroll
                for (int j = 0; j < 2; j++) {
                    int nf = p * 2 + j;
                    mma_f16(s4[nf], ah,  &kbh[2 * j]);
                    mma_f16(s4[nf], ah,  &kbl[2 * j]);
                    mma_f16(s4[nf], al4, &kbh[2 * j]);
                }
            }
        }
        const float cf = SCALE / SOFTCAP;
#pragma unroll
        for (int nf = 0; nf < 4; nf++) {
#pragma unroll
            for (int e = 0; e < 4; e++) {
                int ir = wr + c_row + ((e >> 1) * 8);
                int jc = wc + nf * 8 + c_col + (e & 1);
                float sv = SOFTCAP * tanhf(s4[nf][e] * cf);
                int ig = qi0 + ir, jg = kj0 + jc;
                if (jg > ig || jg < ig - WIN) sv = -1e30f;
                St[ir * STLD + jc] = sv;
            }
        }
        __syncthreads();

        if (kj0 + BK <= qi0) load_k(kj0 + BK);

        // ---- Phase B: softmax ----
        {
            int qr = tid >> 2, sub = tid & 3;
            float mx = -1e30f;
#pragma unroll
            for (int ii = 0; ii < 16; ii++)
                mx = fmaxf(mx, St[qr * STLD + sub * 16 + ii]);
            mx = fmaxf(mx, __shfl_xor_sync(0xffffffffu, mx, 1));
            mx = fmaxf(mx, __shfl_xor_sync(0xffffffffu, mx, 2));
            float mold = rowm[qr];
            float mnew = fmaxf(mold, mx);
            float al   = __expf(mold - mnew);
            float ps   = 0.f;
#pragma unroll
            for (int ii = 0; ii < 16; ii++) {
                float sv = St[qr * STLD + sub * 16 + ii];
                float p  = (sv > -1e29f) ? __expf(sv - mnew) : 0.f;
                __half ph = __float2half(p);
                Pt[qr * PTLD + sub * 16 + ii] = ph;
                ps += __half2float(ph);
            }
            ps += __shfl_xor_sync(0xffffffffu, ps, 1);
            ps += __shfl_xor_sync(0xffffffffu, ps, 2);
            if (sub == 0) {
                rowm[qr] = mnew;
                rowl[qr] = rowl[qr] * al + ps;
                alf[qr]  = al;
            }
        }
        __syncthreads();

        // ---- Phase C: O = diag(alpha) O + P Vh ----
        {
            float a1 = alf[wr + c_row], a2 = alf[wr + c_row + 8];
#pragma unroll
            for (int nf = 0; nf < 16; nf++) {
                o[nf][0] *= a1; o[nf][1] *= a1;
                o[nf][2] *= a2; o[nf][3] *= a2;
            }
#pragma unroll
            for (int kk = 0; kk < BK; kk += 16) {
                uint32_t pf[4];
                ldsm_x4(pf, sPt + ((wr + a_row) * PTLD + kk + a_half) * 2);
#pragma unroll
                for (int dn = 0; dn < 8; dn++) {
                    int d0 = wc2 + dn * 16;
                    uint32_t voff = ((kk + (lane & 15)) * DPAD
                                   + d0 + (lane >> 4) * 8) * 2;
                    uint32_t vbh[4];
                    ldsm_x4t(vbh, sVh + voff);
                    mma_f16(o[dn * 2],     pf, &vbh[0]);
                    mma_f16(o[dn * 2 + 1], pf, &vbh[2]);
                }
            }
        }
        __syncthreads();

        if (kj0 + BK <= qi0) load_v(kj0 + BK);
    }

    // ---- epilogue: normalize, split to fp16 hi/lo, store ----
    {
        int r1 = wr + c_row;
        float i1 = 1.0f / rowl[r1], i2 = 1.0f / rowl[r1 + 8];
        size_t t1 = (size_t)(tok0 + qi0 + r1);
#pragma unroll
        for (int nf = 0; nf < 16; nf++) {
            int col = h * HD + wc2 + nf * 8 + c_col;
            float v0 = o[nf][0] * i1, v1 = o[nf][1] * i1;
            float v2 = o[nf][2] * i2, v3 = o[nf][3] * i2;
            __half h0 = __float2half(v0), h1 = __float2half(v1);
            __half h2 = __float2half(v2), h3 = __float2half(v3);
            *(__half2*)(outH + t1 * ATTW + col) = __halves2half2(h0, h1);
            *(__half2*)(outH + (t1 + 8) * ATTW + col) = __halves2half2(h2, h3);
            *(__half2*)(outL + t1 * ATTW + col) = __halves2half2(
                __float2half(v0 - __half2float(h0)),
                __float2half(v1 - __half2float(h1)));
            *(__half2*)(outL + (t1 + 8) * ATTW + col) = __halves2half2(
                __float2half(v2 - __half2float(h2)),
                __float2half(v3 - __half2float(h3)));
        }
    }
}

// ---------------------------------------------------------------------------
extern "C" void kernel_launch(void* const* d_in, const int* in_sizes, int n_in,
                              void* d_out, int out_size)
{
    const float* hidden = (const float*)d_in[0];
    const float* cosb   = (const float*)d_in[1];
    const float* sinb   = (const float*)d_in[2];
    const float* w_qkv  = (const float*)d_in[3];
    const float* w_o    = (const float*)d_in[4];
    float* out = (float*)d_out;

    float* d_qkv;
    cudaGetSymbolAddress((void**)&d_qkv, g_qkv);
    __half *hH, *hL, *wqH, *aH, *aL, *woH;
    cudaGetSymbolAddress((void**)&hH,  g_hidH);
    cudaGetSymbolAddress((void**)&hL,  g_hidL);
    cudaGetSymbolAddress((void**)&wqH, g_wqH);
    cudaGetSymbolAddress((void**)&aH,  g_aH);
    cudaGetSymbolAddress((void**)&aL,  g_aL);
    cudaGetSymbolAddress((void**)&woH, g_woH);

    cudaFuncSetAttribute(gemm_tc<2>, cudaFuncAttributeMaxDynamicSharedMemorySize,
                         GEMM_SMEM2);
    cudaFuncSetAttribute(attn_kernel, cudaFuncAttributeMaxDynamicSharedMemorySize,
                         ATT_SMEM_BYTES);

    // 0. split activations (hi/lo); weights hi-only (lo planes are dead
    //    in the 2-product AhBh + AlBh scheme)
    {
        size_t n1 = (size_t)TT * HIDDIM;
        size_t n2 = (size_t)QKVW * HIDDIM;
        split_f16<<<(unsigned)((n1 / 4 + 255) / 256), 256>>>(hidden, hH, hL, 1.0f, n1);
        cvt_f16<<<(unsigned)((n2 / 4 + 255) / 256), 256>>>(w_qkv, wqH, WSCALE, n2);
    }

    // 1. QKV projection: single 2-product launch over all 8192 columns
    gemm_tc<2><<<dim3(QKVW / GBN, TT / GBM), 256, GEMM_SMEM2>>>(
        hH, hL, wqH, (const __half*)nullptr, d_qkv, 0, QKVW, HIDDIM, CSCALE);

    // 2. RoPE + fp16 prep of Q/K (hi/lo) and V (hi) planes
    prep_qkv<<<dim3(TT / 8, NH + 2 * NKV), 256>>>(cosb, sinb);

    // 3. Tensor-core sliding-window attention (writes aH/aL directly)
    attn_kernel<<<dim3(SEQ / BQ, NH, NB), 256, ATT_SMEM_BYTES>>>(aH, aL);

    // 4. convert w_o hi-only
    {
        size_t n4 = (size_t)HIDDIM * ATTW;
        cvt_f16<<<(unsigned)((n4 / 4 + 255) / 256), 256>>>(w_o, woH, WSCALE, n4);
    }

    // 5. Output projection (2-product)
    gemm_tc<2><<<dim3(HIDDIM / GBN, TT / GBM), 256, GEMM_SMEM2>>>(
        aH, aL, woH, (const __half*)nullptr, out, 0, HIDDIM, ATTW, CSCALE);
}